// round 17
// baseline (speedup 1.0000x reference)
#include <cuda_runtime.h>
#include <cstdint>
#include <math.h>

// ConvSTFT via windowed FFT-1024 = 16 x 16 x 4, register radix-16,
// real-input packing (two frames per complex FFT), native u64-packed
// f32x2 datapath (zero pack/unpack MOVs on butterflies), AoS u64 smem,
// in-register twiddles (4 parallel chains), MUFU window/twiddles.
// CTA: 8 frames = 4 packed FFTs, 64 threads each (256 threads).

#define TLEN   160000
#define NBATCH 32
#define FRAMES 501
#define NBINS  513
#define HOP    320
#define FPC    8
#define PBLK2  1092              // u64 elems per packed-FFT block (mod 32 == 8 in floats)

typedef unsigned long long u64;

#define K_PP1  0x3F8000003F800000ULL   // (+1, +1)
#define K_MM1  0xBF800000BF800000ULL   // (-1, -1)
#define K_PM1  0xBF8000003F800000ULL   // (lo +1, hi -1)
#define K_MP1  0x3F800000BF800000ULL   // (lo -1, hi +1)
#define K_PPH  0x3F0000003F000000ULL   // (+.5, +.5)
#define K_PMH  0xBF0000003F000000ULL   // (lo +.5, hi -.5)
#define K_C8   0x3F3504F33F3504F3ULL   // (+C8, +C8)
#define K_M8   0xBF3504F3BF3504F3ULL   // (-C8, -C8)

__device__ __forceinline__ u64 pfma(u64 a, u64 k, u64 c) {
    u64 r; asm("fma.rn.f32x2 %0, %1, %2, %3;" : "=l"(r) : "l"(a), "l"(k), "l"(c));
    return r;
}
__device__ __forceinline__ u64 pmul(u64 a, u64 k) {
    u64 r; asm("mul.rn.f32x2 %0, %1, %2;" : "=l"(r) : "l"(a), "l"(k));
    return r;
}
__device__ __forceinline__ u64 padd(u64 a, u64 b) { return pfma(a, K_PP1, b); }
__device__ __forceinline__ u64 psub(u64 a, u64 b) { return pfma(b, K_MM1, a); }
__device__ __forceinline__ u64 pswap(u64 a) {
    u64 r;
    asm("{ .reg .b32 x, y; mov.b64 {x, y}, %1; mov.b64 %0, {y, x}; }"
        : "=l"(r) : "l"(a));
    return r;
}
__device__ __forceinline__ u64 pack2(float x, float y) {
    u64 r; asm("mov.b64 %0, {%1, %2};" : "=l"(r) : "f"(x), "f"(y)); return r;
}
__device__ __forceinline__ void unpack2(u64 a, float& x, float& y) {
    asm("mov.b64 {%0, %1}, %2;" : "=f"(x), "=f"(y) : "l"(a));
}
// packed value * complex constant/register w = (wx, wy)
__device__ __forceinline__ u64 cmulr(u64 a, float wx, float wy) {
    float x, y; unpack2(a, x, y);
    return pack2(x * wx - y * wy, x * wy + y * wx);
}
// scalar complex mul for twiddle chains
__device__ __forceinline__ float2 cmul(float2 a, float2 b) {
    return make_float2(a.x * b.x - a.y * b.y, a.x * b.y + a.y * b.x);
}

__device__ __forceinline__ void r4(u64& a, u64& b, u64& c, u64& d) {
    u64 t0 = padd(a, c), t1 = psub(a, c), t2 = padd(b, d), t3 = psub(b, d);
    a = padd(t0, t2);
    c = psub(t0, t2);
    const u64 t3s = pswap(t3);
    b = pfma(t3s, K_PM1, t1);
    d = pfma(t3s, K_MP1, t1);
}
// FFT-16 in regs; freq f lives at slot ((f&3)<<2) | (f>>2).
__device__ __forceinline__ void fft16(u64 v[16]) {
#pragma unroll
    for (int n2 = 0; n2 < 4; n2++) r4(v[n2], v[n2 + 4], v[n2 + 8], v[n2 + 12]);
    const float c1 = 0.92387953251128674f, s1 = 0.38268343236508977f;
    // full cmuls (odd-angle twiddles)
    v[5]  = cmulr(v[5],  c1, -s1);
    v[7]  = cmulr(v[7],  s1, -c1);
    v[13] = cmulr(v[13], s1, -c1);
    v[15] = cmulr(v[15], -c1, s1);
    // cheap packed identities:
    // W2 = (C8,-C8): r = C8*(x+y, y-x);  t = swap*(1,-1)+v
    v[6]  = pmul(pfma(pswap(v[6]),  K_PM1, v[6]),  K_C8);
    v[9]  = pmul(pfma(pswap(v[9]),  K_PM1, v[9]),  K_C8);
    // W4 = -i: r = (y, -x) = swap*(1,-1)
    v[10] = pmul(pswap(v[10]), K_PM1);
    // W6 = (-C8,-C8): r = -C8*(x-y, y+x); t = swap*(-1,1)+v
    v[11] = pmul(pfma(pswap(v[11]), K_MP1, v[11]), K_M8);
    v[14] = pmul(pfma(pswap(v[14]), K_MP1, v[14]), K_M8);
#pragma unroll
    for (int k1 = 0; k1 < 4; k1++) r4(v[4*k1], v[4*k1+1], v[4*k1+2], v[4*k1+3]);
}
// bin k -> smem slot (stage-C storage permutation, XOR-swizzled for banks)
__device__ __forceinline__ int LOC(int k) {
    const int jg = (k >> 6) & 3;
    return ((k & 15) ^ (jg << 2)) | (jg << 4)
         | (((k >> 4) & 3) << 6) | (((k >> 8) & 3) << 8);
}

__global__ __launch_bounds__(256)
void stft_fft_kernel(const float* __restrict__ x, float* __restrict__ out) {
    extern __shared__ u64 smem[];      // [4][PBLK2]
    const int tid = threadIdx.x;
    const int g   = tid >> 6;          // packed-FFT index 0..3
    const int u   = tid & 63;          // thread within FFT (= n2)
    const int f0  = blockIdx.x * FPC;
    const int b   = blockIdx.y;
    u64* S = smem + g * PBLK2;
    const int fa = f0 + 2 * g, fb = fa + 1;
    const float* xrow = x + (size_t)b * TLEN;
    const bool interior = (blockIdx.x >= 1) && (blockIdx.x <= 61);

    // ---- stage A: load two frames packed (inline Hann window), FFT-16 ----
    const float WSC = 6.2831853071795864f / 799.0f;
    u64 v[16];
    if (interior) {
        const float* pa = xrow + fa * HOP - 512 + u;
#pragma unroll
        for (int n1 = 0; n1 < 16; n1++) {
            const int p = n1 * 64 + u;
            if (n1 == 0 || n1 == 15) {          // window identically zero
                v[n1] = 0ULL;
            } else {
                float w = 0.f;
                if (p >= 112 && p < 912)
                    w = 0.5f - 0.5f * __cosf((float)(p - 112) * WSC);
                v[n1] = pack2(pa[n1 * 64] * w, pa[n1 * 64 + HOP] * w);
            }
        }
    } else {
#pragma unroll
        for (int n1 = 0; n1 < 16; n1++) {
            const int p = n1 * 64 + u;
            if (n1 == 0 || n1 == 15) {
                v[n1] = 0ULL;
            } else {
                float w = 0.f;
                if (p >= 112 && p < 912)
                    w = 0.5f - 0.5f * __cosf((float)(p - 112) * WSC);
                const int xia = fa * HOP + p - 512;
                const int xib = xia + HOP;
                float ra = 0.f, rb = 0.f;
                if (fa < FRAMES && xia >= 0 && xia < TLEN) ra = xrow[xia] * w;
                if (fb < FRAMES && xib >= 0 && xib < TLEN) rb = xrow[xib] * w;
                v[n1] = pack2(ra, rb);
            }
        }
    }
    fft16(v);
    {   // twiddle W_1024^{k1*u}; 4 parallel scalar chains stepping by w^4
        float sn, cs;
        __sincosf((float)u * (6.2831853071795864f / 1024.0f), &sn, &cs);
        const float2 w1 = make_float2(cs, -sn);
        const float2 w2 = cmul(w1, w1);
        const float2 w3 = cmul(w2, w1);
        const float2 w4 = cmul(w2, w2);
        S[u] = v[0];
        float2 t1 = w1, t2 = w2, t3 = w3, t4 = w4;
#pragma unroll
        for (int q = 0; q < 4; q++) {    // k1 = 4q+1 .. 4q+4
            const int k1a = 4 * q + 1, k1b = 4 * q + 2,
                      k1c = 4 * q + 3, k1d = 4 * q + 4;
            S[k1a * 68 + u] = cmulr(v[((k1a & 3) << 2) | (k1a >> 2)], t1.x, t1.y);
            S[k1b * 68 + u] = cmulr(v[((k1b & 3) << 2) | (k1b >> 2)], t2.x, t2.y);
            S[k1c * 68 + u] = cmulr(v[((k1c & 3) << 2) | (k1c >> 2)], t3.x, t3.y);
            if (k1d < 16)
                S[k1d * 68 + u] = cmulr(v[((k1d & 3) << 2) | (k1d >> 2)], t4.x, t4.y);
            if (q < 3) {
                t1 = cmul(t1, w4); t2 = cmul(t2, w4);
                t3 = cmul(t3, w4); t4 = cmul(t4, w4);
            }
        }
    }
    __syncthreads();

    // ---- stage B: FFT-16 over m1 (stride 4) ----
    const int k1 = u >> 2, m2 = u & 3;
#pragma unroll
    for (int m1 = 0; m1 < 16; m1++)
        v[m1] = S[k1 * 68 + 4 * m1 + m2];
    __syncthreads();
    fft16(v);
    {   // twiddle W_64^{j1*m2} = (W_1024^{16*m2})^{j1}; 4 parallel chains
        float sn, cs;
        __sincosf((float)m2 * (6.2831853071795864f / 64.0f), &sn, &cs);
        const float2 w1 = make_float2(cs, -sn);
        const float2 w2 = cmul(w1, w1);
        const float2 w3 = cmul(w2, w1);
        const float2 w4 = cmul(w2, w2);
        S[k1 * 4 + m2] = v[0];
        float2 t1 = w1, t2 = w2, t3 = w3, t4 = w4;
#pragma unroll
        for (int q = 0; q < 4; q++) {
            const int j1a = 4 * q + 1, j1b = 4 * q + 2,
                      j1c = 4 * q + 3, j1d = 4 * q + 4;
            S[j1a * 64 + k1 * 4 + m2] = cmulr(v[((j1a & 3) << 2) | (j1a >> 2)], t1.x, t1.y);
            S[j1b * 64 + k1 * 4 + m2] = cmulr(v[((j1b & 3) << 2) | (j1b >> 2)], t2.x, t2.y);
            S[j1c * 64 + k1 * 4 + m2] = cmulr(v[((j1c & 3) << 2) | (j1c >> 2)], t3.x, t3.y);
            if (j1d < 16)
                S[j1d * 64 + k1 * 4 + m2] = cmulr(v[((j1d & 3) << 2) | (j1d >> 2)], t4.x, t4.y);
            if (q < 3) {
                t1 = cmul(t1, w4); t2 = cmul(t2, w4);
                t3 = cmul(t3, w4); t4 = cmul(t4, w4);
            }
        }
    }
    __syncthreads();

    // ---- stage C: radix-4 over m2; all 1024 bins to smem (permuted) ----
    const int jg = u & 3, k1c = u >> 2;
    u64 d[4][4];
#pragma unroll
    for (int dj = 0; dj < 4; dj++)
#pragma unroll
        for (int dm = 0; dm < 4; dm++) {     // rotated m2 -> conflict-free
            const int m2r = (jg + dm) & 3;
            d[dj][m2r] = S[(4 * jg + dj) * 64 + k1c * 4 + m2r];
        }
    __syncthreads();
    const int locbase = (k1c ^ (jg << 2)) | (jg << 4);
#pragma unroll
    for (int dj = 0; dj < 4; dj++) {
        r4(d[dj][0], d[dj][1], d[dj][2], d[dj][3]);   // bins kap + 256*j2
#pragma unroll
        for (int j2 = 0; j2 < 4; j2++)
            S[locbase + (dj << 6) + (j2 << 8)] = d[dj][j2];
    }
    __syncthreads();

    // ---- unpack (packed) + coalesced store (32-bit addressing) ----
    u64* o8 = (u64*)out;
    const int p     = tid & 3;
    const int kbase = tid >> 2;            // 0..63
    const u64* Sp = smem + p * PBLK2;
    const int ffa = f0 + 2 * p;
    const unsigned orow = (unsigned)b * (NBINS * FRAMES) + (unsigned)ffa;
#pragma unroll
    for (int it = 0; it < 8; it++) {
        const int k  = kbase + 64 * it;    // 0..511
        const int kb = (1024 - k) & 1023;
        const u64 z1 = Sp[LOC(k)];
        const u64 z2 = Sp[LOC(kb)];
        // Xa = z1*(.5,.5) + z2*(.5,-.5);  Xb = sw(z1)*(.5,-.5) + sw(z2)*(.5,.5)
        const u64 Xa = pfma(z1, K_PPH, pmul(z2, K_PMH));
        const u64 Xb = pfma(pswap(z1), K_PMH, pmul(pswap(z2), K_PPH));
        const unsigned base = orow + (unsigned)k * FRAMES;
        if (interior) {
            o8[base]     = Xa;
            o8[base + 1] = Xb;
        } else {
            if (ffa < FRAMES)     o8[base]     = Xa;
            if (ffa + 1 < FRAMES) o8[base + 1] = Xb;
        }
    }
    if (tid < 4) {                         // bin 512 (self-conjugate)
        float zx, zy;
        unpack2(smem[tid * PBLK2 + LOC(512)], zx, zy);
        const int ff = f0 + 2 * tid;
        const unsigned base = (unsigned)b * (NBINS * FRAMES)
                            + 512u * FRAMES + (unsigned)ff;
        if (interior) {
            o8[base]     = pack2(zx, 0.f);
            o8[base + 1] = pack2(zy, 0.f);
        } else {
            if (ff < FRAMES)     o8[base]     = pack2(zx, 0.f);
            if (ff + 1 < FRAMES) o8[base + 1] = pack2(zy, 0.f);
        }
    }
}

extern "C" void kernel_launch(void* const* d_in, const int* in_sizes, int n_in,
                              void* d_out, int out_size) {
    const float* x = (const float*)d_in[0];
    float* out     = (float*)d_out;

    const int smem_bytes = 4 * PBLK2 * sizeof(u64);   // 34944
    cudaFuncSetAttribute(stft_fft_kernel,
                         cudaFuncAttributeMaxDynamicSharedMemorySize, smem_bytes);
    dim3 grid((FRAMES + FPC - 1) / FPC,   // 63
              NBATCH);                    // 32
    stft_fft_kernel<<<grid, 256, smem_bytes>>>(x, out);
}